// round 4
// baseline (speedup 1.0000x reference)
#include <cuda_runtime.h>
#include <math.h>

// VAE_RNN: B=4096, T=200, D=128, L=64, H=128, cin=2L+D=256.
// Persistent kernel: 128 CTAs x 256 threads; each CTA owns 32 batch rows for
// all 200 steps. R4: 8-row register tiles + K-split reductions to cut l1tex
// bytes/MAC (measured bottleneck). Packed fma.rn.f32x2 throughout.

#define NB 4096
#define NT 200
#define ND 128
#define NL 64
#define M_ROWS 32
#define THREADS 256
#define NBLOCKS (NB / M_ROWS)   // 128

// ---- shared memory layout (float offsets) ----
#define OFF_W2CAT 0           // [128][128]  (ug_w2 | rg_w2)   16384 fl
#define OFF_WNS2  16384       // [128][128]  ns_w2             16384
#define OFF_G1T   32768       // [256][32]   G1^T; scratch3/4   8192
#define OFF_HCT   40960       // [128][32]   hc^T; scratch1a/2  4096
#define OFF_XT    45056       // [128][32]   x^T; later G2^T    4096
#define OFF_YT    49152       // [64][32]    y^T                2048
#define OFF_ST    51200       // [64][32]    s^T                2048
#define OFF_UT    53248       // [64][32]    u^T; scratch1b     2048
#define OFF_RT    55296       // [64][32]    r^T; scratch1b     2048
#define OFF_B1C   57344       // [256]
#define OFF_B2C   57600       // [128]
#define OFF_BN1   57728       // [128]
#define OFF_BN2   57856       // [128]
#define SMEM_FLOATS 57984     // 231,936 bytes

typedef unsigned long long u64;

__device__ __forceinline__ u64 dup2(float x) {
    u64 r; unsigned xi = __float_as_uint(x);
    asm("mov.b64 %0, {%1, %1};" : "=l"(r) : "r"(xi));
    return r;
}
__device__ __forceinline__ void fma2(u64& c, u64 a, u64 b) {
    asm("fma.rn.f32x2 %0, %1, %2, %0;" : "+l"(c) : "l"(a), "l"(b));
}
__device__ __forceinline__ u64 add2(u64 a, u64 b) {
    u64 r;
    asm("add.rn.f32x2 %0, %1, %2;" : "=l"(r) : "l"(a), "l"(b));
    return r;
}
__device__ __forceinline__ float2 unpk(u64 v) {
    unsigned lo, hi;
    asm("mov.b64 {%0, %1}, %2;" : "=r"(lo), "=r"(hi) : "l"(v));
    return make_float2(__uint_as_float(lo), __uint_as_float(hi));
}
__device__ __forceinline__ float fast_tanhf(float x) {
    float ax = fabsf(x);
    float e  = __expf(-2.0f * ax);
    float t  = __fdividef(1.0f - e, 1.0f + e);
    return copysignf(t, x);
}
__device__ __forceinline__ float fast_sigmoidf(float x) {
    return __fdividef(1.0f, 1.0f + __expf(-x));
}

__global__ void __launch_bounds__(THREADS, 1) vae_rnn_kernel(
    const float* __restrict__ data,
    const float* __restrict__ ug_w1, const float* __restrict__ ug_b1,
    const float* __restrict__ ug_w2, const float* __restrict__ ug_b2,
    const float* __restrict__ rg_w1, const float* __restrict__ rg_b1,
    const float* __restrict__ rg_w2, const float* __restrict__ rg_b2,
    const float* __restrict__ ns_w1, const float* __restrict__ ns_b1,
    const float* __restrict__ ns_w2, const float* __restrict__ ns_b2,
    float* __restrict__ out)
{
    extern __shared__ float sm[];
    float* W2cat = sm + OFF_W2CAT;
    float* Wns2  = sm + OFF_WNS2;
    float* g1T   = sm + OFF_G1T;
    float* hcT   = sm + OFF_HCT;
    float* xT    = sm + OFF_XT;     // doubles as G2^T
    float* yT    = sm + OFF_YT;
    float* sT    = sm + OFF_ST;
    float* uT    = sm + OFF_UT;
    float* rT    = sm + OFF_RT;
    float* b1c   = sm + OFF_B1C;
    float* b2c   = sm + OFF_B2C;
    float* bn1   = sm + OFF_BN1;
    float* bn2   = sm + OFF_BN2;

    const int tid = threadIdx.x;
    const int b0  = blockIdx.x * M_ROWS;

    // ---- one-time init ----
    for (int i = tid; i < 128 * 128; i += THREADS) {
        int k = i >> 7, n = i & 127;
        W2cat[i] = (n < 64) ? ug_w2[k * 64 + n] : rg_w2[k * 64 + (n - 64)];
        Wns2[i]  = ns_w2[i];
    }
    if (tid < 256)
        b1c[tid] = (tid < 128) ? ug_b1[tid] : rg_b1[tid - 128];
    if (tid < 128) {
        b2c[tid] = (tid < 64) ? ug_b2[tid] : rg_b2[tid - 64];
        bn1[tid] = ns_b1[tid];
        bn2[tid] = ns_b2[tid];
    }
    for (int i = tid; i < NL * M_ROWS; i += THREADS) { yT[i] = 0.0f; sT[i] = 0.0f; }
    __syncthreads();

    // ---- thread decompositions ----
    const int kg = tid >> 7;       // 0..1  (GEMM1/2/4 K-split)
    const int g  = tid & 127;
    const int mg = g & 3;          // 8-row slab: rows mg*8..mg*8+7
    const int ng = g >> 2;         // 0..31
    const int kg3 = tid >> 6;      // 0..3  (GEMM3 K-split)
    const int g3  = tid & 63;
    const int mg3 = g3 & 3;
    const int ng3 = g3 >> 2;       // 0..15

    // GEMM1 weight column base (8 cols), with kg row offset
    const float* w1col = (ng < 16) ? (ug_w1 + ng * 8) : (rg_w1 + (ng - 16) * 8);
    const float* w1kg  = w1col + (size_t)kg * 128 * 128;

    const float4* yT4 = (const float4*)yT;
    const float4* sT4 = (const float4*)sT;
    const float4* xT4 = (const float4*)xT;
    const float4* hcT4 = (const float4*)hcT;
    const float4* g1T4c = (const float4*)g1T;

    // scratch pointers (u64 views of dead regions)
    u64* scr_hc = (u64*)hcT;            // 2048 u64
    u64* scr_ur = (u64*)uT;             // 2048 u64 (uT+rT contiguous)
    u64* scr_g1 = (u64*)g1T;            // 4096 u64 (G1T); +hcT = 6144 contiguous

    const float* xbase = data + (size_t)b0 * NT * ND;
    const int xm  = tid & 31;
    const int xdg = tid >> 5;           // 0..7 -> d = xdg*16..+16

    for (int t = 0; t < NT; ++t) {
        // ---- load x tile transposed: xT[d][m] ----
        {
            const float4* src = (const float4*)(xbase + (size_t)xm * (NT * ND) + t * ND + xdg * 16);
            float4 v0 = __ldg(src + 0);
            float4 v1 = __ldg(src + 1);
            float4 v2 = __ldg(src + 2);
            float4 v3 = __ldg(src + 3);
            float vals[16] = { v0.x, v0.y, v0.z, v0.w, v1.x, v1.y, v1.z, v1.w,
                               v2.x, v2.y, v2.z, v2.w, v3.x, v3.y, v3.z, v3.w };
            int base = (xdg * 16) * 32 + xm;
            #pragma unroll
            for (int j = 0; j < 16; ++j) xT[base + j * 32] = vals[j];
        }
        __syncthreads();   // S1

        // ===== GEMM1: G1[32x256] = tanh([y|s|x] @ W1 + b1), 8mx8n, 2-way K =====
        {
            u64 acc[8][4];
            #pragma unroll
            for (int m = 0; m < 8; ++m)
                #pragma unroll
                for (int j = 0; j < 4; ++j) acc[m][j] = 0ull;

            const float4* A0 = (kg == 0) ? yT4 : xT4;           // k-rows 0..63 of slab
            const float4* A1 = (kg == 0) ? sT4 : (xT4 + 64 * 8); // k-rows 64..127

            #pragma unroll 2
            for (int i = 0; i < 64; ++i) {
                float4 a0 = A0[i * 8 + mg * 2];
                float4 a1 = A0[i * 8 + mg * 2 + 1];
                const ulonglong2* wp = (const ulonglong2*)(w1kg + (size_t)i * 128);
                ulonglong2 wA = __ldg(wp);
                ulonglong2 wB = __ldg(wp + 1);
                u64 ad[8] = { dup2(a0.x), dup2(a0.y), dup2(a0.z), dup2(a0.w),
                              dup2(a1.x), dup2(a1.y), dup2(a1.z), dup2(a1.w) };
                #pragma unroll
                for (int m = 0; m < 8; ++m) {
                    fma2(acc[m][0], ad[m], wA.x); fma2(acc[m][1], ad[m], wA.y);
                    fma2(acc[m][2], ad[m], wB.x); fma2(acc[m][3], ad[m], wB.y);
                }
            }
            #pragma unroll 2
            for (int i = 0; i < 64; ++i) {
                float4 a0 = A1[i * 8 + mg * 2];
                float4 a1 = A1[i * 8 + mg * 2 + 1];
                const ulonglong2* wp = (const ulonglong2*)(w1kg + (size_t)(i + 64) * 128);
                ulonglong2 wA = __ldg(wp);
                ulonglong2 wB = __ldg(wp + 1);
                u64 ad[8] = { dup2(a0.x), dup2(a0.y), dup2(a0.z), dup2(a0.w),
                              dup2(a1.x), dup2(a1.y), dup2(a1.z), dup2(a1.w) };
                #pragma unroll
                for (int m = 0; m < 8; ++m) {
                    fma2(acc[m][0], ad[m], wA.x); fma2(acc[m][1], ad[m], wA.y);
                    fma2(acc[m][2], ad[m], wB.x); fma2(acc[m][3], ad[m], wB.y);
                }
            }
            // kg==1 writes partials into dead regions (hcT for g<64, uT/rT for g>=64)
            if (kg == 1) {
                u64* sp = (g < 64) ? (scr_hc + g * 32) : (scr_ur + (g - 64) * 32);
                #pragma unroll
                for (int m = 0; m < 8; ++m)
                    #pragma unroll
                    for (int j = 0; j < 4; ++j) sp[m * 4 + j] = acc[m][j];
            }
            __syncthreads();   // S2
            if (kg == 0) {
                u64* sp = (g < 64) ? (scr_hc + g * 32) : (scr_ur + (g - 64) * 32);
                #pragma unroll
                for (int m = 0; m < 8; ++m)
                    #pragma unroll
                    for (int j = 0; j < 4; ++j) acc[m][j] = add2(acc[m][j], sp[m * 4 + j]);
                #pragma unroll
                for (int j = 0; j < 4; ++j) {
                    int c0 = ng * 8 + 2 * j;
                    float bA = b1c[c0], bB = b1c[c0 + 1];
                    float tA[8], tB[8];
                    #pragma unroll
                    for (int m = 0; m < 8; ++m) {
                        float2 v = unpk(acc[m][j]);
                        tA[m] = fast_tanhf(v.x + bA);
                        tB[m] = fast_tanhf(v.y + bB);
                    }
                    float4* dA = (float4*)(g1T + c0 * 32 + mg * 8);
                    dA[0] = make_float4(tA[0], tA[1], tA[2], tA[3]);
                    dA[1] = make_float4(tA[4], tA[5], tA[6], tA[7]);
                    float4* dB = (float4*)(g1T + (c0 + 1) * 32 + mg * 8);
                    dB[0] = make_float4(tB[0], tB[1], tB[2], tB[3]);
                    dB[1] = make_float4(tB[4], tB[5], tB[6], tB[7]);
                }
            }
        }
        __syncthreads();   // S3

        // ===== GEMM2: [u|r][32x128] = sigmoid(G1 @ W2 + b2), 8mx4n, 2-way K =====
        {
            const int isR = (ng >= 16);
            const int c0 = (ng & 15) * 4;
            const float4* Ab = g1T4c + (isR ? 128 * 8 : 0);
            const int wcol = (isR ? 64 : 0) + c0;

            u64 acc2[8][2];
            #pragma unroll
            for (int m = 0; m < 8; ++m) { acc2[m][0] = 0ull; acc2[m][1] = 0ull; }

            #pragma unroll 2
            for (int i = 0; i < 64; ++i) {
                int kk = kg * 64 + i;
                float4 a0 = Ab[kk * 8 + mg * 2];
                float4 a1 = Ab[kk * 8 + mg * 2 + 1];
                ulonglong2 w = *(const ulonglong2*)(W2cat + kk * 128 + wcol);
                u64 ad[8] = { dup2(a0.x), dup2(a0.y), dup2(a0.z), dup2(a0.w),
                              dup2(a1.x), dup2(a1.y), dup2(a1.z), dup2(a1.w) };
                #pragma unroll
                for (int m = 0; m < 8; ++m) {
                    fma2(acc2[m][0], ad[m], w.x); fma2(acc2[m][1], ad[m], w.y);
                }
            }
            if (kg == 1) {
                u64* sp = scr_hc + g * 16;
                #pragma unroll
                for (int m = 0; m < 8; ++m) {
                    sp[m * 2 + 0] = acc2[m][0]; sp[m * 2 + 1] = acc2[m][1];
                }
            }
            __syncthreads();   // S4
            if (kg == 0) {
                u64* sp = scr_hc + g * 16;
                #pragma unroll
                for (int m = 0; m < 8; ++m) {
                    acc2[m][0] = add2(acc2[m][0], sp[m * 2 + 0]);
                    acc2[m][1] = add2(acc2[m][1], sp[m * 2 + 1]);
                }
                float* dst = (isR ? rT : uT) + c0 * 32 + mg * 8;
                #pragma unroll
                for (int j = 0; j < 2; ++j) {
                    float bA = b2c[(isR ? 64 : 0) * 0 + (isR ? 64 : 0) + c0 + 2 * j];
                    float bB = b2c[(isR ? 64 : 0) + c0 + 2 * j + 1];
                    float qA[8], qB[8];
                    #pragma unroll
                    for (int m = 0; m < 8; ++m) {
                        float2 v = unpk(acc2[m][j]);
                        qA[m] = fast_sigmoidf(v.x + bA);
                        qB[m] = fast_sigmoidf(v.y + bB);
                    }
                    float4* dA = (float4*)(dst + (2 * j) * 32);
                    dA[0] = make_float4(qA[0], qA[1], qA[2], qA[3]);
                    dA[1] = make_float4(qA[4], qA[5], qA[6], qA[7]);
                    float4* dB = (float4*)(dst + (2 * j + 1) * 32);
                    dB[0] = make_float4(qB[0], qB[1], qB[2], qB[3]);
                    dB[1] = make_float4(qB[4], qB[5], qB[6], qB[7]);
                }
            }
        }
        __syncthreads();   // S5

        // ---- build hcT = [y*r | s*r] ----
        {
            float4* hc4 = (float4*)hcT;
            const float4* r4 = (const float4*)rT;
            #pragma unroll
            for (int i = 0; i < 4; ++i) {
                int flat = tid + i * THREADS;      // 0..1023 float4s
                int k = flat >> 3, mq = flat & 7;  // k 0..127, mq = m/4
                float4 rv = r4[(k & 63) * 8 + mq];
                float4 v = (k < 64) ? yT4[k * 8 + mq] : sT4[(k - 64) * 8 + mq];
                hc4[flat] = make_float4(v.x * rv.x, v.y * rv.y, v.z * rv.z, v.w * rv.w);
            }
        }
        __syncthreads();   // S6

        // ===== GEMM3: G2[32x128] = tanh([hc|x] @ ns_w1 + bn1), 8mx8n, 4-way K =====
        {
            u64 acc3[8][4];
            #pragma unroll
            for (int m = 0; m < 8; ++m)
                #pragma unroll
                for (int j = 0; j < 4; ++j) acc3[m][j] = 0ull;

            const float4* A = ((kg3 < 2) ? hcT4 : xT4) + ((kg3 & 1) * 64) * 8;
            const float* wbase = ns_w1 + (size_t)(kg3 * 64) * 128 + ng3 * 8;

            #pragma unroll 2
            for (int i = 0; i < 64; ++i) {
                float4 a0 = A[i * 8 + mg3 * 2];
                float4 a1 = A[i * 8 + mg3 * 2 + 1];
                const ulonglong2* wp = (const ulonglong2*)(wbase + (size_t)i * 128);
                ulonglong2 wA = __ldg(wp);
                ulonglong2 wB = __ldg(wp + 1);
                u64 ad[8] = { dup2(a0.x), dup2(a0.y), dup2(a0.z), dup2(a0.w),
                              dup2(a1.x), dup2(a1.y), dup2(a1.z), dup2(a1.w) };
                #pragma unroll
                for (int m = 0; m < 8; ++m) {
                    fma2(acc3[m][0], ad[m], wA.x); fma2(acc3[m][1], ad[m], wA.y);
                    fma2(acc3[m][2], ad[m], wB.x); fma2(acc3[m][3], ad[m], wB.y);
                }
            }
            __syncthreads();   // S7 (G1T+hcT must be dead before scratch writes)
            if (kg3 >= 1) {
                u64* sp = scr_g1 + ((size_t)(kg3 - 1) * 64 + g3) * 32;
                #pragma unroll
                for (int m = 0; m < 8; ++m)
                    #pragma unroll
                    for (int j = 0; j < 4; ++j) sp[m * 4 + j] = acc3[m][j];
            }
            __syncthreads();   // S8
            if (kg3 == 0) {
                #pragma unroll
                for (int p = 0; p < 3; ++p) {
                    u64* sp = scr_g1 + ((size_t)p * 64 + g3) * 32;
                    #pragma unroll
                    for (int m = 0; m < 8; ++m)
                        #pragma unroll
                        for (int j = 0; j < 4; ++j) acc3[m][j] = add2(acc3[m][j], sp[m * 4 + j]);
                }
                float* g2T = xT;   // reuse xT region as G2^T
                #pragma unroll
                for (int j = 0; j < 4; ++j) {
                    int c0 = ng3 * 8 + 2 * j;
                    float bA = bn1[c0], bB = bn1[c0 + 1];
                    float tA[8], tB[8];
                    #pragma unroll
                    for (int m = 0; m < 8; ++m) {
                        float2 v = unpk(acc3[m][j]);
                        tA[m] = fast_tanhf(v.x + bA);
                        tB[m] = fast_tanhf(v.y + bB);
                    }
                    float4* dA = (float4*)(g2T + c0 * 32 + mg3 * 8);
                    dA[0] = make_float4(tA[0], tA[1], tA[2], tA[3]);
                    dA[1] = make_float4(tA[4], tA[5], tA[6], tA[7]);
                    float4* dB = (float4*)(g2T + (c0 + 1) * 32 + mg3 * 8);
                    dB[0] = make_float4(tB[0], tB[1], tB[2], tB[3]);
                    dB[1] = make_float4(tB[4], tB[5], tB[6], tB[7]);
                }
            }
        }
        __syncthreads();   // S9

        // ===== GEMM4: ns[32x128] = G2 @ ns_w2 + bn2; gated update. 8mx4n, 2-way K =====
        {
            const int n0 = ng * 4;
            u64 acc4[8][2];
            #pragma unroll
            for (int m = 0; m < 8; ++m) { acc4[m][0] = 0ull; acc4[m][1] = 0ull; }

            #pragma unroll 2
            for (int i = 0; i < 64; ++i) {
                int kk = kg * 64 + i;
                float4 a0 = xT4[kk * 8 + mg * 2];      // G2^T lives in xT
                float4 a1 = xT4[kk * 8 + mg * 2 + 1];
                ulonglong2 w = *(const ulonglong2*)(Wns2 + kk * 128 + n0);
                u64 ad[8] = { dup2(a0.x), dup2(a0.y), dup2(a0.z), dup2(a0.w),
                              dup2(a1.x), dup2(a1.y), dup2(a1.z), dup2(a1.w) };
                #pragma unroll
                for (int m = 0; m < 8; ++m) {
                    fma2(acc4[m][0], ad[m], w.x); fma2(acc4[m][1], ad[m], w.y);
                }
            }
            if (kg == 1) {
                u64* sp = scr_g1 + g * 16;
                #pragma unroll
                for (int m = 0; m < 8; ++m) {
                    sp[m * 2 + 0] = acc4[m][0]; sp[m * 2 + 1] = acc4[m][1];
                }
            }
            __syncthreads();   // S10
            if (kg == 0) {
                u64* sp = scr_g1 + g * 16;
                #pragma unroll
                for (int m = 0; m < 8; ++m) {
                    acc4[m][0] = add2(acc4[m][0], sp[m * 2 + 0]);
                    acc4[m][1] = add2(acc4[m][1], sp[m * 2 + 1]);
                }
                #pragma unroll
                for (int j = 0; j < 2; ++j) {
                    #pragma unroll
                    for (int h = 0; h < 2; ++h) {
                        int n = n0 + 2 * j + h;
                        int l = n & 63;
                        float bb = bn2[n];
                        float* st = (n < 64) ? yT : sT;
                        int base = l * 32 + mg * 8;
                        #pragma unroll
                        for (int m = 0; m < 8; ++m) {
                            float2 v = unpk(acc4[m][j]);
                            float raw = (h == 0 ? v.x : v.y) + bb;
                            float nv = (n < 64) ? raw : fabsf(raw);
                            float u = uT[base + m];
                            float old = st[base + m];
                            st[base + m] = (1.0f - u) * nv + u * old;
                        }
                    }
                }
            }
        }
        __syncthreads();   // S11
    }

    // ---- write output: y (4096x64) then s (4096x64), row-major ----
    for (int i = tid; i < M_ROWS * NL; i += THREADS) {
        int m = i >> 6, l = i & 63;
        out[(size_t)(b0 + m) * NL + l] = yT[l * 32 + m];
        out[(size_t)NB * NL + (size_t)(b0 + m) * NL + l] = sT[l * 32 + m];
    }
}

extern "C" void kernel_launch(void* const* d_in, const int* in_sizes, int n_in,
                              void* d_out, int out_size) {
    const float* data  = (const float*)d_in[0];
    // d_in[1] = time_steps (unused by the reference)
    const float* ug_w1 = (const float*)d_in[2];
    const float* ug_b1 = (const float*)d_in[3];
    const float* ug_w2 = (const float*)d_in[4];
    const float* ug_b2 = (const float*)d_in[5];
    const float* rg_w1 = (const float*)d_in[6];
    const float* rg_b1 = (const float*)d_in[7];
    const float* rg_w2 = (const float*)d_in[8];
    const float* rg_b2 = (const float*)d_in[9];
    const float* ns_w1 = (const float*)d_in[10];
    const float* ns_b1 = (const float*)d_in[11];
    const float* ns_w2 = (const float*)d_in[12];
    const float* ns_b2 = (const float*)d_in[13];
    float* out = (float*)d_out;

    size_t smem_bytes = (size_t)SMEM_FLOATS * sizeof(float);
    cudaFuncSetAttribute(vae_rnn_kernel,
                         cudaFuncAttributeMaxDynamicSharedMemorySize,
                         (int)smem_bytes);
    vae_rnn_kernel<<<NBLOCKS, THREADS, smem_bytes>>>(
        data,
        ug_w1, ug_b1, ug_w2, ug_b2,
        rg_w1, rg_b1, rg_w2, rg_b2,
        ns_w1, ns_b1, ns_w2, ns_b2,
        out);
}